// round 2
// baseline (speedup 1.0000x reference)
#include <cuda_runtime.h>
#include <cuda_bf16.h>

#define B_  32
#define C_  256
#define HW_ 64
#define AS_ 8
#define T_  64    // AS*AS
#define NBT 2048  // B_*T_

typedef unsigned long long ull;

// ---------------- f32x2 packed helpers (sm_103a) ----------------
__device__ __forceinline__ ull pack2(float lo, float hi) {
    ull r; asm("mov.b64 %0, {%1, %2};" : "=l"(r) : "f"(lo), "f"(hi)); return r;
}
__device__ __forceinline__ void unpack2(float& lo, float& hi, ull v) {
    asm("mov.b64 {%0, %1}, %2;" : "=f"(lo), "=f"(hi) : "l"(v));
}
__device__ __forceinline__ void fma2(ull& d, ull a, ull b) {
    asm("fma.rn.f32x2 %0, %1, %2, %0;" : "+l"(d) : "l"(a), "l"(b));
}

// ---------------- scratch (device globals; every element rewritten each call) ----------------
// pooled / projected tensors stored channel-major: [c][b*T + t]
__device__ float g_PR[C_ * NBT];
__device__ float g_PD[C_ * NBT];
__device__ float g_Q [C_ * NBT];
__device__ float g_K [C_ * NBT];
__device__ float g_V [C_ * NBT];
__device__ float g_Apart[4 * B_ * T_ * T_];  // 4 c-slices of 64
__device__ float g_A [B_ * T_ * T_];
__device__ float g_F [C_ * NBT];             // Fatt, [c][b*T + t]

// ---------------- 1) 8x8 avg pool of both inputs ----------------
// grid: 2*B*C blocks, 128 threads; each block pools one 64x64 plane.
__global__ void pool_kernel(const float* __restrict__ Frgb, const float* __restrict__ Fd) {
    int bid   = blockIdx.x;
    int which = bid >> 13;
    int plane = bid & 8191;            // b*C + c
    int b = plane >> 8, c = plane & 255;
    const float* src = (which ? Fd : Frgb) + (size_t)plane * (HW_ * HW_);
    float* dst = (which ? g_PD : g_PR) + (size_t)c * NBT + b * T_;

    __shared__ float part[128];
    int t = threadIdx.x;
    int chunk = t & 15;                // float4 index along w
    int i     = t >> 4;                // pooled row 0..7
    const float4* p = (const float4*)src;
    float s = 0.f;
#pragma unroll
    for (int r = 0; r < 8; r++) {
        float4 v = p[(i * 8 + r) * 16 + chunk];
        s += (v.x + v.y) + (v.z + v.w);
    }
    part[t] = s;
    __syncthreads();
    if (t < 64) {
        int pi = t >> 3, pj = t & 7;
        dst[t] = (part[pi * 16 + 2 * pj] + part[pi * 16 + 2 * pj + 1]) * (1.0f / 64.0f);
    }
}

// ---------------- 2) QKV mega-GEMM: Out[o][n] = sum_c W[o][c] * P[c][n] + bias[o] ----------------
// M=256, N=2048, K=256. grid (8 m-tiles of 32, 16 n-tiles of 128, 3), 128 threads.
// micro-tile per thread: 4m x 8n as 4x4 f32x2 accumulators.
__global__ void qkv_kernel(const float* __restrict__ Wq, const float* __restrict__ bq,
                           const float* __restrict__ Wk, const float* __restrict__ bk,
                           const float* __restrict__ Wv, const float* __restrict__ bv) {
    int m0g = blockIdx.x * 32;
    int n0g = blockIdx.y * 128;
    int z   = blockIdx.z;
    const float* W; const float* bias; const float* P; float* Out;
    if (z == 0)      { W = Wq; bias = bq; P = g_PR; Out = g_Q; }
    else if (z == 1) { W = Wk; bias = bk; P = g_PD; Out = g_K; }
    else             { W = Wv; bias = bv; P = g_PD; Out = g_V; }

    __shared__ float Wst[32][36];   // transposed: [k][m], padded
    __shared__ float Xs[32][128];   // [k][n]

    int tid = threadIdx.x;
    int ty = tid >> 4;              // 0..7  -> m0 = ty*4
    int tx = tid & 15;              // 0..15 -> n0 = tx*8
    int m0 = ty * 4, n0 = tx * 8;

    ull acc[4][4];
#pragma unroll
    for (int i = 0; i < 4; i++)
#pragma unroll
        for (int j = 0; j < 4; j++) acc[i][j] = 0ull;

    for (int kc = 0; kc < C_; kc += 32) {
        // W tile [32m][32k] -> transposed into Wst[k][m]
#pragma unroll
        for (int q = 0; q < 2; q++) {
            int l = tid + q * 128;               // 0..255 float4
            int row = l >> 3, c4 = l & 7;
            float4 v = *(const float4*)&W[(m0g + row) * C_ + kc + c4 * 4];
            Wst[c4 * 4 + 0][row] = v.x; Wst[c4 * 4 + 1][row] = v.y;
            Wst[c4 * 4 + 2][row] = v.z; Wst[c4 * 4 + 3][row] = v.w;
        }
        // X tile [32k][128n]
#pragma unroll
        for (int q = 0; q < 8; q++) {
            int l = tid + q * 128;               // 0..1023 float4
            int row = l >> 5, c4 = l & 31;
            *(float4*)&Xs[row][c4 * 4] = *(const float4*)&P[(size_t)(kc + row) * NBT + n0g + c4 * 4];
        }
        __syncthreads();
#pragma unroll
        for (int k = 0; k < 32; k++) {
            float4 a4 = *(const float4*)&Wst[k][m0];
            ull a0 = pack2(a4.x, a4.x), a1 = pack2(a4.y, a4.y);
            ull a2 = pack2(a4.z, a4.z), a3 = pack2(a4.w, a4.w);
#pragma unroll
            for (int j = 0; j < 4; j++) {
                ull bj = *(const ull*)&Xs[k][n0 + 2 * j];
                fma2(acc[0][j], a0, bj);
                fma2(acc[1][j], a1, bj);
                fma2(acc[2][j], a2, bj);
                fma2(acc[3][j], a3, bj);
            }
        }
        __syncthreads();
    }

#pragma unroll
    for (int i = 0; i < 4; i++) {
        int m = m0g + m0 + i;
        float bb = bias[m];
        float r[8];
#pragma unroll
        for (int j = 0; j < 4; j++) {
            float lo, hi; unpack2(lo, hi, acc[i][j]);
            r[2 * j] = lo + bb; r[2 * j + 1] = hi + bb;
        }
        float* Op = &Out[(size_t)m * NBT + n0g + n0];
        *(float4*)&Op[0] = make_float4(r[0], r[1], r[2], r[3]);
        *(float4*)&Op[4] = make_float4(r[4], r[5], r[6], r[7]);
    }
}

// ---------------- 3) partial A: A_p[b][t][s] = sum_{c in 64-slice} Q[c][bt+t] K[c][bt+s] ----------------
// grid (B, 4), 256 threads; 4t x 4s per thread as f32x2.
__global__ void attn_partial_kernel() {
    int b = blockIdx.x;
    int c0 = blockIdx.y * 64;
    __shared__ float Qs[64][64];
    __shared__ float Ks[64][64];
    int tid = threadIdx.x;
#pragma unroll
    for (int q = 0; q < 4; q++) {
        int l = tid + q * 256;                  // 0..1023 float4
        int row = l >> 4, c4 = l & 15;
        *(float4*)&Qs[row][c4 * 4] = *(const float4*)&g_Q[(size_t)(c0 + row) * NBT + b * T_ + c4 * 4];
    }
#pragma unroll
    for (int q = 0; q < 4; q++) {
        int l = tid + q * 256;
        int row = l >> 4, c4 = l & 15;
        *(float4*)&Ks[row][c4 * 4] = *(const float4*)&g_K[(size_t)(c0 + row) * NBT + b * T_ + c4 * 4];
    }
    __syncthreads();
    int m0 = (tid >> 4) * 4;   // t
    int n0 = (tid & 15) * 4;   // s
    ull acc[4][2];
#pragma unroll
    for (int i = 0; i < 4; i++) { acc[i][0] = 0ull; acc[i][1] = 0ull; }
#pragma unroll
    for (int k = 0; k < 64; k++) {
        float4 a4 = *(const float4*)&Qs[k][m0];
        ull a0 = pack2(a4.x, a4.x), a1 = pack2(a4.y, a4.y);
        ull a2 = pack2(a4.z, a4.z), a3 = pack2(a4.w, a4.w);
        ull b0 = *(const ull*)&Ks[k][n0];
        ull b1 = *(const ull*)&Ks[k][n0 + 2];
        fma2(acc[0][0], a0, b0); fma2(acc[0][1], a0, b1);
        fma2(acc[1][0], a1, b0); fma2(acc[1][1], a1, b1);
        fma2(acc[2][0], a2, b0); fma2(acc[2][1], a2, b1);
        fma2(acc[3][0], a3, b0); fma2(acc[3][1], a3, b1);
    }
    float* Ap = g_Apart + (((size_t)blockIdx.y * B_ + b) * (T_ * T_));
#pragma unroll
    for (int i = 0; i < 4; i++) {
        float x0, x1, x2, x3;
        unpack2(x0, x1, acc[i][0]);
        unpack2(x2, x3, acc[i][1]);
        *(float4*)&Ap[(m0 + i) * T_ + n0] = make_float4(x0, x1, x2, x3);
    }
}

// ---------------- 4) reduce 4 partials + row softmax ----------------
// grid (B, 4): 16 rows per block, 256 threads (8 warps, 2 rows/warp).
__global__ void softmax_kernel() {
    int b  = blockIdx.x;
    int r0 = blockIdx.y * 16;
    int tid = threadIdx.x;
    int warp = tid >> 5, lane = tid & 31;
#pragma unroll
    for (int rr = 0; rr < 2; rr++) {
        int r = r0 + warp * 2 + rr;
        size_t base = (size_t)b * (T_ * T_) + r * T_;
        float v0 = 0.f, v1 = 0.f;
#pragma unroll
        for (int p = 0; p < 4; p++) {
            size_t pb = ((size_t)p * B_) * (T_ * T_) + base;
            v0 += g_Apart[pb + lane];
            v1 += g_Apart[pb + lane + 32];
        }
        float m = fmaxf(v0, v1);
#pragma unroll
        for (int off = 16; off; off >>= 1) m = fmaxf(m, __shfl_xor_sync(0xffffffffu, m, off));
        float e0 = __expf(v0 - m), e1 = __expf(v1 - m);
        float s = e0 + e1;
#pragma unroll
        for (int off = 16; off; off >>= 1) s += __shfl_xor_sync(0xffffffffu, s, off);
        float inv = 1.0f / s;
        g_A[base + lane]      = e0 * inv;
        g_A[base + lane + 32] = e1 * inv;
    }
}

// ---------------- 5) Fatt[c][bt+t] = sum_s V[c][bt+s] * A[b][t][s] ----------------
// grid (B, 8 chunks of 32 channels), 256 threads.
__global__ void fatt_kernel() {
    int b = blockIdx.x, cc = blockIdx.y;
    __shared__ float As[64][68];
    __shared__ float Vs[32][64];
    int tid = threadIdx.x;
    const float* Ab = g_A + ((size_t)b * T_ * T_);
#pragma unroll
    for (int q = 0; q < 4; q++) {
        int l = tid + q * 256;
        int row = l >> 4, c4 = l & 15;
        *(float4*)&As[row][c4 * 4] = *(const float4*)&Ab[row * T_ + c4 * 4];
    }
#pragma unroll
    for (int q = 0; q < 2; q++) {
        int l = tid + q * 256;
        int row = l >> 4, c4 = l & 15;
        *(float4*)&Vs[row][c4 * 4] =
            *(const float4*)&g_V[(size_t)(cc * 32 + row) * NBT + b * T_ + c4 * 4];
    }
    __syncthreads();
    int cl = tid >> 3;
    int t0 = tid & 7;
    float acc[8] = {};
#pragma unroll
    for (int s4 = 0; s4 < 16; s4++) {
        float4 v = *(const float4*)&Vs[cl][s4 * 4];
#pragma unroll
        for (int j = 0; j < 8; j++) {
            float4 a = *(const float4*)&As[t0 + 8 * j][s4 * 4];
            acc[j] = fmaf(v.x, a.x, acc[j]);
            acc[j] = fmaf(v.y, a.y, acc[j]);
            acc[j] = fmaf(v.z, a.z, acc[j]);
            acc[j] = fmaf(v.w, a.w, acc[j]);
        }
    }
    float* Fb = g_F + (size_t)(cc * 32 + cl) * NBT + b * T_;
#pragma unroll
    for (int j = 0; j < 8; j++) Fb[t0 + 8 * j] = acc[j];
}

// ---------------- 6) bilinear upsample (half-pixel) + blend, float4 I/O ----------------
// grid B*C blocks, 256 threads (one 64x64 plane each).
__global__ void upsample_blend_kernel(const float* __restrict__ Frgb,
                                      const float* __restrict__ alphap,
                                      float* __restrict__ out) {
    int plane = blockIdx.x;            // b*C + c
    int b = plane >> 8, c = plane & 255;
    __shared__ float Fs[64];
    __shared__ int   i0s[64];
    __shared__ int   i1s[64];
    __shared__ float fs[64];
    int tid = threadIdx.x;
    if (tid < 64) {
        Fs[tid] = g_F[(size_t)c * NBT + b * T_ + tid];
        float s  = (tid + 0.5f) * 0.125f - 0.5f;
        float fl = floorf(s);
        int   i0 = (int)fl;
        fs[tid]  = s - fl;
        i0s[tid] = i0 < 0 ? 0 : i0;
        i1s[tid] = (i0 + 1) > 7 ? 7 : (i0 + 1);
    }
    __syncthreads();
    float alpha = *alphap;
    float beta  = 1.0f - alpha;
    const float4* rp = (const float4*)(Frgb + (size_t)plane * (HW_ * HW_));
    float4*       op = (float4*)(out  + (size_t)plane * (HW_ * HW_));
#pragma unroll
    for (int q = 0; q < 4; q++) {
        int i4 = tid + q * 256;        // float4 index 0..1023
        int h  = i4 >> 4;
        int w0 = (i4 & 15) * 4;
        int   y0 = i0s[h], y1 = i1s[h]; float fy = fs[h];
        float4 r = rp[i4];
        float res[4];
#pragma unroll
        for (int j = 0; j < 4; j++) {
            int w = w0 + j;
            int   x0 = i0s[w], x1 = i1s[w]; float fx = fs[w];
            float v00 = Fs[y0 * 8 + x0], v01 = Fs[y0 * 8 + x1];
            float v10 = Fs[y1 * 8 + x0], v11 = Fs[y1 * 8 + x1];
            float top = v00 + fx * (v01 - v00);
            float bot = v10 + fx * (v11 - v10);
            res[j] = top + fy * (bot - top);
        }
        float4 o;
        o.x = alpha * res[0] + beta * r.x;
        o.y = alpha * res[1] + beta * r.y;
        o.z = alpha * res[2] + beta * r.z;
        o.w = alpha * res[3] + beta * r.w;
        op[i4] = o;
    }
}

// ---------------- launch ----------------
extern "C" void kernel_launch(void* const* d_in, const int* in_sizes, int n_in,
                              void* d_out, int out_size) {
    const float* Frgb  = (const float*)d_in[0];
    const float* Fd    = (const float*)d_in[1];
    const float* Wq    = (const float*)d_in[2];
    const float* bq    = (const float*)d_in[3];
    const float* Wk    = (const float*)d_in[4];
    const float* bk    = (const float*)d_in[5];
    const float* Wv    = (const float*)d_in[6];
    const float* bv    = (const float*)d_in[7];
    const float* alpha = (const float*)d_in[8];
    float* out = (float*)d_out;

    pool_kernel<<<2 * B_ * C_, 128>>>(Frgb, Fd);
    qkv_kernel<<<dim3(8, 16, 3), 128>>>(Wq, bq, Wk, bk, Wv, bv);
    attn_partial_kernel<<<dim3(B_, 4), 256>>>();
    softmax_kernel<<<dim3(B_, 4), 256>>>();
    fatt_kernel<<<dim3(B_, 8), 256>>>();
    upsample_blend_kernel<<<B_ * C_, 256>>>(Frgb, alpha, out);
}

// round 3
// speedup vs baseline: 1.0735x; 1.0735x over previous
#include <cuda_runtime.h>
#include <cuda_bf16.h>

#define B_  32
#define C_  256
#define HW_ 64
#define AS_ 8
#define T_  64    // AS*AS
#define CT_ (C_ * T_)

typedef unsigned long long ull;

// ---------------- f32x2 packed helpers (sm_103a) ----------------
__device__ __forceinline__ ull pack2(float lo, float hi) {
    ull r; asm("mov.b64 %0, {%1, %2};" : "=l"(r) : "f"(lo), "f"(hi)); return r;
}
__device__ __forceinline__ void unpack2(float& lo, float& hi, ull v) {
    asm("mov.b64 {%0, %1}, %2;" : "=f"(lo), "=f"(hi) : "l"(v));
}
__device__ __forceinline__ void fma2(ull& d, ull a, ull b) {
    asm("fma.rn.f32x2 %0, %1, %2, %0;" : "+l"(d) : "l"(a), "l"(b));
}

// ---------------- scratch (device globals; all batch-major [b][c][t]) ----------------
__device__ float g_PR[B_ * CT_];
__device__ float g_PD[B_ * CT_];
__device__ float g_Q [B_ * CT_];
__device__ float g_K [B_ * CT_];
__device__ float g_V [B_ * CT_];
__device__ float g_Apart[4 * B_ * T_ * T_];  // 4 c-slices of 64
__device__ float g_A [B_ * T_ * T_];
__device__ float g_F [B_ * CT_];

// ---------------- 1) 8x8 avg pool. F_d planes first, F_rgb last (L2 residency for blend) ----
// grid: 2*B*C blocks, 128 threads; one 64x64 plane each.
__global__ void pool_kernel(const float* __restrict__ Frgb, const float* __restrict__ Fd) {
    int bid   = blockIdx.x;
    int which = bid >> 13;            // 0: F_d (read first), 1: F_rgb (read last -> stays in L2)
    int plane = bid & 8191;           // b*C + c
    const float* src = (which ? Frgb : Fd) + (size_t)plane * (HW_ * HW_);
    float* dst = (which ? g_PR : g_PD) + (size_t)plane * T_;

    __shared__ float part[128];
    int t = threadIdx.x;
    int chunk = t & 15;               // float4 along w
    int i     = t >> 4;               // pooled row 0..7
    const float4* p = (const float4*)src;
    float s = 0.f;
#pragma unroll
    for (int r = 0; r < 8; r++) {
        float4 v = p[(i * 8 + r) * 16 + chunk];
        s += (v.x + v.y) + (v.z + v.w);
    }
    part[t] = s;
    __syncthreads();
    if (t < 64) {
        int pi = t >> 3, pj = t & 7;
        dst[t] = (part[pi * 16 + 2 * pj] + part[pi * 16 + 2 * pj + 1]) * (1.0f / 64.0f);
    }
}

// ---------------- 2) QKV: Out[b][o][t] = sum_c W[o][c] * P[b][c][t] + bias[o] ----------------
// grid (B, 4 m-tiles of 64, 3), 256 threads. 4m x 4n micro-tile, f32x2 accumulators.
__global__ void qkv_kernel(const float* __restrict__ Wq, const float* __restrict__ bq,
                           const float* __restrict__ Wk, const float* __restrict__ bk,
                           const float* __restrict__ Wv, const float* __restrict__ bv) {
    int b  = blockIdx.x;
    int o0 = blockIdx.y * 64;
    int z  = blockIdx.z;
    const float* W; const float* bias; const float* P; float* Out;
    if (z == 0)      { W = Wq; bias = bq; P = g_PR; Out = g_Q; }
    else if (z == 1) { W = Wk; bias = bk; P = g_PD; Out = g_K; }
    else             { W = Wv; bias = bv; P = g_PD; Out = g_V; }

    __shared__ float Wst[32][68];   // transposed [k][m], padded (68 % 4 == 0 keeps 16B align)
    __shared__ float Xs[32][64];    // [k][t]

    int tid = threadIdx.x;
    int m0 = (tid >> 4) * 4;        // 16 m-groups * 4
    int n0 = (tid & 15) * 4;        // 16 n-groups * 4
    const float* Pb = P + ((size_t)b * CT_);

    ull acc[4][2];
#pragma unroll
    for (int i = 0; i < 4; i++) { acc[i][0] = 0ull; acc[i][1] = 0ull; }

    for (int kc = 0; kc < C_; kc += 32) {
        // W tile [64m][32k] -> transposed into Wst[k][m]
#pragma unroll
        for (int q = 0; q < 2; q++) {
            int l = tid + q * 256;             // 0..511 float4
            int row = l >> 3, c4 = l & 7;
            float4 v = *(const float4*)&W[(o0 + row) * C_ + kc + c4 * 4];
            Wst[c4 * 4 + 0][row] = v.x; Wst[c4 * 4 + 1][row] = v.y;
            Wst[c4 * 4 + 2][row] = v.z; Wst[c4 * 4 + 3][row] = v.w;
        }
        // X tile [32k][64t]
#pragma unroll
        for (int q = 0; q < 2; q++) {
            int l = tid + q * 256;             // 0..511 float4
            int row = l >> 4, c4 = l & 15;
            *(float4*)&Xs[row][c4 * 4] = *(const float4*)&Pb[(size_t)(kc + row) * T_ + c4 * 4];
        }
        __syncthreads();
#pragma unroll
        for (int k = 0; k < 32; k++) {
            float4 a4 = *(const float4*)&Wst[k][m0];
            ull a0 = pack2(a4.x, a4.x), a1 = pack2(a4.y, a4.y);
            ull a2 = pack2(a4.z, a4.z), a3 = pack2(a4.w, a4.w);
            ull b0 = *(const ull*)&Xs[k][n0];
            ull b1 = *(const ull*)&Xs[k][n0 + 2];
            fma2(acc[0][0], a0, b0); fma2(acc[0][1], a0, b1);
            fma2(acc[1][0], a1, b0); fma2(acc[1][1], a1, b1);
            fma2(acc[2][0], a2, b0); fma2(acc[2][1], a2, b1);
            fma2(acc[3][0], a3, b0); fma2(acc[3][1], a3, b1);
        }
        __syncthreads();
    }

    float* Ob = Out + ((size_t)b * CT_);
#pragma unroll
    for (int i = 0; i < 4; i++) {
        float bb = bias[o0 + m0 + i];
        float x0, x1, x2, x3;
        unpack2(x0, x1, acc[i][0]);
        unpack2(x2, x3, acc[i][1]);
        *(float4*)&Ob[(size_t)(o0 + m0 + i) * T_ + n0] =
            make_float4(x0 + bb, x1 + bb, x2 + bb, x3 + bb);
    }
}

// ---------------- 3) partial A: A_p[b][t][s] = sum_{c in 64-slice} Q[b][c][t] K[b][c][s] ------
// grid (B, 4), 256 threads; 4t x 4s per thread, f32x2.
__global__ void attn_partial_kernel() {
    int b  = blockIdx.x;
    int c0 = blockIdx.y * 64;
    __shared__ float Qs[64][64];
    __shared__ float Ks[64][64];
    int tid = threadIdx.x;
    const float* Qb = g_Q + ((size_t)b * CT_) + (size_t)c0 * T_;
    const float* Kb = g_K + ((size_t)b * CT_) + (size_t)c0 * T_;
#pragma unroll
    for (int q = 0; q < 4; q++) {
        int l = tid + q * 256;                 // 0..1023 float4
        int row = l >> 4, c4 = l & 15;
        *(float4*)&Qs[row][c4 * 4] = *(const float4*)&Qb[(size_t)row * T_ + c4 * 4];
    }
#pragma unroll
    for (int q = 0; q < 4; q++) {
        int l = tid + q * 256;
        int row = l >> 4, c4 = l & 15;
        *(float4*)&Ks[row][c4 * 4] = *(const float4*)&Kb[(size_t)row * T_ + c4 * 4];
    }
    __syncthreads();
    int m0 = (tid >> 4) * 4;   // t
    int n0 = (tid & 15) * 4;   // s
    ull acc[4][2];
#pragma unroll
    for (int i = 0; i < 4; i++) { acc[i][0] = 0ull; acc[i][1] = 0ull; }
#pragma unroll
    for (int k = 0; k < 64; k++) {
        float4 a4 = *(const float4*)&Qs[k][m0];
        ull a0 = pack2(a4.x, a4.x), a1 = pack2(a4.y, a4.y);
        ull a2 = pack2(a4.z, a4.z), a3 = pack2(a4.w, a4.w);
        ull b0 = *(const ull*)&Ks[k][n0];
        ull b1 = *(const ull*)&Ks[k][n0 + 2];
        fma2(acc[0][0], a0, b0); fma2(acc[0][1], a0, b1);
        fma2(acc[1][0], a1, b0); fma2(acc[1][1], a1, b1);
        fma2(acc[2][0], a2, b0); fma2(acc[2][1], a2, b1);
        fma2(acc[3][0], a3, b0); fma2(acc[3][1], a3, b1);
    }
    float* Ap = g_Apart + (((size_t)blockIdx.y * B_ + b) * (T_ * T_));
#pragma unroll
    for (int i = 0; i < 4; i++) {
        float x0, x1, x2, x3;
        unpack2(x0, x1, acc[i][0]);
        unpack2(x2, x3, acc[i][1]);
        *(float4*)&Ap[(m0 + i) * T_ + n0] = make_float4(x0, x1, x2, x3);
    }
}

// ---------------- 4) reduce 4 partials + row softmax ----------------
// grid (B, 4): 16 rows per block, 256 threads (8 warps, 2 rows/warp).
__global__ void softmax_kernel() {
    int b  = blockIdx.x;
    int r0 = blockIdx.y * 16;
    int tid = threadIdx.x;
    int warp = tid >> 5, lane = tid & 31;
#pragma unroll
    for (int rr = 0; rr < 2; rr++) {
        int r = r0 + warp * 2 + rr;
        size_t base = (size_t)b * (T_ * T_) + r * T_;
        float v0 = 0.f, v1 = 0.f;
#pragma unroll
        for (int p = 0; p < 4; p++) {
            size_t pb = ((size_t)p * B_) * (T_ * T_) + base;
            v0 += g_Apart[pb + lane];
            v1 += g_Apart[pb + lane + 32];
        }
        float m = fmaxf(v0, v1);
#pragma unroll
        for (int off = 16; off; off >>= 1) m = fmaxf(m, __shfl_xor_sync(0xffffffffu, m, off));
        float e0 = __expf(v0 - m), e1 = __expf(v1 - m);
        float s = e0 + e1;
#pragma unroll
        for (int off = 16; off; off >>= 1) s += __shfl_xor_sync(0xffffffffu, s, off);
        float inv = 1.0f / s;
        g_A[base + lane]      = e0 * inv;
        g_A[base + lane + 32] = e1 * inv;
    }
}

// ---------------- 5) Fatt[b][c][t] = sum_s V[b][c][s] * A[b][t][s] ----------------
// grid (B, 8 chunks of 32 channels), 256 threads.
__global__ void fatt_kernel() {
    int b = blockIdx.x, cc = blockIdx.y;
    __shared__ float As[64][68];
    __shared__ float Vs[32][64];
    int tid = threadIdx.x;
    const float* Ab = g_A + ((size_t)b * T_ * T_);
#pragma unroll
    for (int q = 0; q < 4; q++) {
        int l = tid + q * 256;
        int row = l >> 4, c4 = l & 15;
        *(float4*)&As[row][c4 * 4] = *(const float4*)&Ab[row * T_ + c4 * 4];
    }
    const float* Vb = g_V + ((size_t)b * CT_) + (size_t)cc * 32 * T_;
#pragma unroll
    for (int q = 0; q < 2; q++) {
        int l = tid + q * 256;
        int row = l >> 4, c4 = l & 15;
        *(float4*)&Vs[row][c4 * 4] = *(const float4*)&Vb[(size_t)row * T_ + c4 * 4];
    }
    __syncthreads();
    int cl = tid >> 3;
    int t0 = tid & 7;
    float acc[8] = {};
#pragma unroll
    for (int s4 = 0; s4 < 16; s4++) {
        float4 v = *(const float4*)&Vs[cl][s4 * 4];
#pragma unroll
        for (int j = 0; j < 8; j++) {
            float4 a = *(const float4*)&As[t0 + 8 * j][s4 * 4];
            acc[j] = fmaf(v.x, a.x, acc[j]);
            acc[j] = fmaf(v.y, a.y, acc[j]);
            acc[j] = fmaf(v.z, a.z, acc[j]);
            acc[j] = fmaf(v.w, a.w, acc[j]);
        }
    }
    float* Fb = g_F + ((size_t)b * CT_) + (size_t)(cc * 32 + cl) * T_;
#pragma unroll
    for (int j = 0; j < 8; j++) Fb[t0 + 8 * j] = acc[j];
}

// ---------------- 6) bilinear upsample + blend, float4 I/O, DESCENDING plane order ----------
// grid B*C blocks, 256 threads (one 64x64 plane each).
__global__ void upsample_blend_kernel(const float* __restrict__ Frgb,
                                      const float* __restrict__ alphap,
                                      float* __restrict__ out) {
    int plane = (B_ * C_ - 1) - blockIdx.x;   // reverse order: hit F_rgb tail still in L2
    __shared__ float Fs[64];
    __shared__ int   i0s[64];
    __shared__ int   i1s[64];
    __shared__ float fs[64];
    int tid = threadIdx.x;
    if (tid < 64) {
        Fs[tid] = g_F[(size_t)plane * T_ + tid];
        float s  = (tid + 0.5f) * 0.125f - 0.5f;
        float fl = floorf(s);
        int   i0 = (int)fl;
        fs[tid]  = s - fl;
        i0s[tid] = i0 < 0 ? 0 : i0;
        i1s[tid] = (i0 + 1) > 7 ? 7 : (i0 + 1);
    }
    __syncthreads();
    float alpha = *alphap;
    float beta  = 1.0f - alpha;
    const float4* rp = (const float4*)(Frgb + (size_t)plane * (HW_ * HW_));
    float4*       op = (float4*)(out  + (size_t)plane * (HW_ * HW_));
#pragma unroll
    for (int q = 0; q < 4; q++) {
        int i4 = tid + q * 256;        // float4 index 0..1023
        int h  = i4 >> 4;
        int w0 = (i4 & 15) * 4;
        int   y0 = i0s[h], y1 = i1s[h]; float fy = fs[h];
        float4 r = rp[i4];
        float res[4];
#pragma unroll
        for (int j = 0; j < 4; j++) {
            int w = w0 + j;
            int   x0 = i0s[w], x1 = i1s[w]; float fx = fs[w];
            float v00 = Fs[y0 * 8 + x0], v01 = Fs[y0 * 8 + x1];
            float v10 = Fs[y1 * 8 + x0], v11 = Fs[y1 * 8 + x1];
            float top = v00 + fx * (v01 - v00);
            float bot = v10 + fx * (v11 - v10);
            res[j] = top + fy * (bot - top);
        }
        float4 o;
        o.x = alpha * res[0] + beta * r.x;
        o.y = alpha * res[1] + beta * r.y;
        o.z = alpha * res[2] + beta * r.z;
        o.w = alpha * res[3] + beta * r.w;
        op[i4] = o;
    }
}

// ---------------- launch ----------------
extern "C" void kernel_launch(void* const* d_in, const int* in_sizes, int n_in,
                              void* d_out, int out_size) {
    const float* Frgb  = (const float*)d_in[0];
    const float* Fd    = (const float*)d_in[1];
    const float* Wq    = (const float*)d_in[2];
    const float* bq    = (const float*)d_in[3];
    const float* Wk    = (const float*)d_in[4];
    const float* bk    = (const float*)d_in[5];
    const float* Wv    = (const float*)d_in[6];
    const float* bv    = (const float*)d_in[7];
    const float* alpha = (const float*)d_in[8];
    float* out = (float*)d_out;

    pool_kernel<<<2 * B_ * C_, 128>>>(Frgb, Fd);
    qkv_kernel<<<dim3(B_, 4, 3), 256>>>(Wq, bq, Wk, bk, Wv, bv);
    attn_partial_kernel<<<dim3(B_, 4), 256>>>();
    softmax_kernel<<<dim3(B_, 4), 256>>>();
    fatt_kernel<<<dim3(B_, 8), 256>>>();
    upsample_blend_kernel<<<B_ * C_, 256>>>(Frgb, alpha, out);
}